// round 12
// baseline (speedup 1.0000x reference)
#include <cuda_runtime.h>
#include <cuda_fp16.h>
#include <cstdint>
#include <cstddef>

// ===================== problem constants =====================
constexpr int C    = 128;            // channels
constexpr int NET  = 7;              // edge types
constexpr int NMAX = 100000;
constexpr int NSEGMAX = NMAX * NET;  // 700000
constexpr int EMAX = 700000;
constexpr int SCAN_BLK = 1024;

// ===================== device scratch ========================
__device__ unsigned g_cnt[NSEGMAX];             // zero-init; re-zeroed by scan
__device__ unsigned g_off[NSEGMAX + 1];         // CSR offsets
__device__ unsigned g_cur[NSEGMAX];             // fill cursors
__device__ int      g_elist[EMAX];              // col index per CSR slot
__device__ unsigned g_ticket;                   // zero-init; re-zeroed by fill
__device__ unsigned long long g_state[1024];    // zero-init; re-zeroed by fill
__device__ float    g_stats[2 * C];             // zero-init; re-zeroed by bnfin
__device__ float    g_scale[C];
__device__ float    g_shift[C];
__device__ uint32_t g_wh[NET * C * C / 2];      // W as fp16 pairs [t][k][n/2]

// ===================== helpers ===============================
__device__ __forceinline__ uint32_t pack_h2(float a, float b) {
    __half2 h = __floats2half2_rn(a, b);
    return *reinterpret_cast<uint32_t*>(&h);
}
__device__ __forceinline__ uint32_t smem_u32(const void* p) {
    uint32_t a;
    asm("{ .reg .u64 t; cvta.to.shared.u64 t, %1; cvt.u32.u64 %0, t; }" : "=r"(a) : "l"(p));
    return a;
}
__device__ __forceinline__ void mma_f16(float* d, const uint32_t* a, uint32_t b0, uint32_t b1) {
    asm volatile(
        "mma.sync.aligned.m16n8k16.row.col.f32.f16.f16.f32 "
        "{%0,%1,%2,%3}, {%4,%5,%6,%7}, {%8,%9}, {%0,%1,%2,%3};"
        : "+f"(d[0]), "+f"(d[1]), "+f"(d[2]), "+f"(d[3])
        : "r"(a[0]), "r"(a[1]), "r"(a[2]), "r"(a[3]), "r"(b0), "r"(b1));
}
#define LDSM_X4(r, addr)                                                        \
    asm volatile("ldmatrix.sync.aligned.m8n8.x4.shared.b16 {%0,%1,%2,%3}, [%4];"\
        : "=r"((r)[0]), "=r"((r)[1]), "=r"((r)[2]), "=r"((r)[3]) : "r"(addr))
#define LDSM_X4_T(r, addr)                                                      \
    asm volatile("ldmatrix.sync.aligned.m8n8.x4.trans.shared.b16 {%0,%1,%2,%3}, [%4];"\
        : "=r"((r)[0]), "=r"((r)[1]), "=r"((r)[2]), "=r"((r)[3]) : "r"(addr))
__device__ __forceinline__ void cp_async16(uint32_t dst, const void* src) {
    asm volatile("cp.async.cg.shared.global [%0], [%1], 16;" :: "r"(dst), "l"(src));
}
#define CP_COMMIT() asm volatile("cp.async.commit_group;" ::: "memory")
#define CP_WAIT0()  asm volatile("cp.async.wait_group 0;" ::: "memory")

__device__ unsigned block_incl_scan(unsigned v, unsigned* wsum) {
    int lane = threadIdx.x & 31, wid = threadIdx.x >> 5;
#pragma unroll
    for (int d = 1; d < 32; d <<= 1) {
        unsigned n = __shfl_up_sync(0xffffffff, v, d);
        if (lane >= d) v += n;
    }
    if (lane == 31) wsum[wid] = v;
    __syncthreads();
    if (wid == 0) {
        unsigned w = wsum[lane];
#pragma unroll
        for (int d = 1; d < 32; d <<= 1) {
            unsigned n = __shfl_up_sync(0xffffffff, w, d);
            if (lane >= d) w += n;
        }
        wsum[lane] = w;
    }
    __syncthreads();
    return v + (wid > 0 ? wsum[wid - 1] : 0u);
}

// ===================== CSR build =============================
// also converts W to fp16 (first 57344 threads)
__global__ void count_kernel(const int* __restrict__ row,
                             const int* __restrict__ et,
                             const float* __restrict__ w, int E) {
    int e = blockIdx.x * blockDim.x + threadIdx.x;
    if (e < NET * C * C / 2) {
        float2 v = reinterpret_cast<const float2*>(w)[e];
        g_wh[e] = pack_h2(v.x, v.y);
    }
    if (e >= E) return;
    int t = et[e];
    if (t == NET - 1) return;
    atomicAdd(&g_cnt[row[e] * NET + t], 1u);
}

// single-pass decoupled-lookback exclusive scan; also re-zeroes g_cnt
__global__ void __launch_bounds__(SCAN_BLK) scan_kernel(int nseg) {
    __shared__ unsigned wsum[32];
    __shared__ unsigned s_bid, s_total, s_prefix;
    int tid = threadIdx.x;
    if (tid == 0) s_bid = atomicAdd(&g_ticket, 1u);
    __syncthreads();
    unsigned bid = s_bid;
    int i = bid * SCAN_BLK + tid;
    unsigned v = (i < nseg) ? g_cnt[i] : 0u;
    if (i < nseg) g_cnt[i] = 0u;                 // restore for next replay
    unsigned incl = block_incl_scan(v, wsum);
    if (tid == SCAN_BLK - 1) s_total = incl;
    __syncthreads();
    if (tid == 0) {
        unsigned total = s_total;
        if (bid == 0) {
            atomicExch(&g_state[0], (2ULL << 32) | (unsigned long long)total);
            s_prefix = 0u;
        } else {
            atomicExch(&g_state[bid], (1ULL << 32) | (unsigned long long)total);
            unsigned running = 0u;
            int idx = (int)bid - 1;
            while (true) {
                unsigned long long s;
                do { s = atomicAdd(&g_state[idx], 0ULL); } while ((unsigned)(s >> 32) == 0u);
                running += (unsigned)s;
                if ((unsigned)(s >> 32) == 2u) break;
                --idx;
            }
            s_prefix = running;
            atomicExch(&g_state[bid], (2ULL << 32) | (unsigned long long)(running + total));
        }
    }
    __syncthreads();
    unsigned off = s_prefix + incl - v;
    if (i < nseg) {
        g_off[i] = off;
        g_cur[i] = off;
        if (i == nseg - 1) g_off[nseg] = off + v;
    }
}

// fill CSR edge list; also re-zeroes scan state for next replay
__global__ void fill_kernel(const int* __restrict__ row,
                            const int* __restrict__ col,
                            const int* __restrict__ et, int E) {
    int e = blockIdx.x * blockDim.x + threadIdx.x;
    if (e < 1024) g_state[e] = 0ULL;
    if (e == 0) g_ticket = 0u;
    if (e >= E) return;
    int t = et[e];
    if (t == NET - 1) return;
    int seg = row[e] * NET + t;
    unsigned pos = atomicAdd(&g_cur[seg], 1u);
    g_elist[pos] = col[e];
}

// ===================== fused aggregate + GEMM + stats ========
constexpr int APITCH = 68;       // uints per A row (272 B: ldmatrix-aligned)
constexpr int BPITCH = 68;       // uints per B k-row
constexpr int ECAP   = 4096;
constexpr int OFF_AS = 0;
constexpr int OFF_BS = OFF_AS + 128 * APITCH;      // 8704
constexpr int OFF_EL = OFF_BS + 128 * BPITCH;      // 17408
constexpr int OFF_SOFF = OFF_EL + ECAP;            // 21504
constexpr int OFF_STAT = OFF_SOFF + 128 * 8;       // 22528
constexpr int SMEM_UINTS = OFF_STAT + 2 * C;       // 22784
constexpr size_t FUSED_SMEM = (size_t)SMEM_UINTS * 4;   // 91136 B

__global__ void __launch_bounds__(512, 2)
fused_kernel(const float* __restrict__ x, float* __restrict__ out, int nrows) {
    extern __shared__ uint32_t smu[];
    uint32_t* As = smu + OFF_AS;
    int*      selist = reinterpret_cast<int*>(smu + OFF_EL);
    unsigned* soff = smu + OFF_SOFF;
    float*    sstat = reinterpret_cast<float*>(smu + OFF_STAT);

    const int tid = threadIdx.x;
    const int wid = tid >> 5, lane = tid & 31;
    const int m0 = blockIdx.x * 128;
    const int rlim = min(128, nrows - m0);
    const float4* x4 = reinterpret_cast<const float4*>(x);

    if (tid < 2 * C) sstat[tid] = 0.f;

    // ---- stage CTA segment offsets ----
#pragma unroll
    for (int i = 0; i < 2; ++i) {
        int idx = tid + i * 512;
        int r = idx >> 3, j = idx & 7;
        soff[idx] = (r < rlim) ? g_off[(m0 + r) * NET + j] : 0u;
    }
    __syncthreads();
    const unsigned e0   = soff[0];
    const unsigned etot = soff[(rlim - 1) * 8 + 7] - e0;
    for (unsigned i = tid; i < min(etot, (unsigned)ECAP); i += 512)
        selist[i] = g_elist[e0 + i];
    __syncthreads();

    const int wm = (wid >> 2) * 32, wn = (wid & 3) * 32;
    const int gr = lane >> 2, gc = lane & 3;
    const int grp = lane >> 3, rr = lane & 7;

    const uint32_t sbase = smem_u32(smu);
    const uint32_t abase = sbase + OFF_AS * 4;
    const uint32_t bbase = sbase + OFF_BS * 4;
    uint32_t aadr0 = abase + (wm + (grp & 1) * 8 + rr) * APITCH * 4 + (grp >> 1) * 16;
    uint32_t aadr1 = aadr0 + 16 * APITCH * 4;
    uint32_t badr0 = bbase + ((grp & 1) * 8 + rr) * BPITCH * 4 + (wn + (grp >> 1) * 8) * 2;
    uint32_t badr1 = badr0 + 16 * 2;

    float acc[2][4][4];
#pragma unroll
    for (int f = 0; f < 2; ++f)
#pragma unroll
        for (int g = 0; g < 4; ++g)
#pragma unroll
            for (int q = 0; q < 4; ++q) acc[f][g][q] = 0.f;

    for (int t = 0; t < NET; ++t) {
        // ---- B_t via cp.async (overlaps the whole gather below) ----
#pragma unroll
        for (int j = 0; j < 4; ++j) {
            int cidx = tid + j * 512;            // 0..2047 16B-chunks
            int k = cidx >> 4, pos = cidx & 15;
            cp_async16(bbase + k * BPITCH * 4 + pos * 16,
                       (const char*)g_wh + (size_t)(t * 8192 + k * 64 + pos * 4) * 4);
        }
        CP_COMMIT();

        // ---- A_t gather: lockstep 4 rows for MLP ----
        if (t == NET - 1) {
#pragma unroll
            for (int i = 0; i < 8; ++i) {
                int r = wid * 8 + i;
                float4 val = make_float4(0.f, 0.f, 0.f, 0.f);
                if (r < rlim) val = x4[(size_t)(m0 + r) * 32 + lane];
                *reinterpret_cast<uint2*>(&As[r * APITCH + 2 * lane]) =
                    make_uint2(pack_h2(val.x, val.y), pack_h2(val.z, val.w));
            }
        } else {
#pragma unroll
            for (int h = 0; h < 2; ++h) {
                int rb = wid * 8 + h * 4;
                unsigned ep[4], ee[4];
                float4 va[4];
#pragma unroll
                for (int j = 0; j < 4; ++j) {
                    int r = rb + j;
                    if (r < rlim) {
                        ep[j] = soff[r * 8 + t] - e0;
                        ee[j] = soff[r * 8 + t + 1] - e0;
                    } else { ep[j] = ee[j] = 0u; }
                    va[j] = make_float4(0.f, 0.f, 0.f, 0.f);
                }
                float inv[4];
#pragma unroll
                for (int j = 0; j < 4; ++j) {
                    unsigned n = ee[j] - ep[j];
                    inv[j] = 1.0f / (float)(n > 1u ? n : 1u);
                }
                while (true) {
                    bool act[4]; float4 v[4];
                    unsigned any = 0u;
#pragma unroll
                    for (int j = 0; j < 4; ++j) {      // batched independent loads
                        act[j] = ep[j] < ee[j];
                        if (act[j]) {
                            unsigned e = ep[j];
                            int c = (e < (unsigned)ECAP) ? selist[e] : g_elist[e0 + e];
                            v[j] = x4[(size_t)c * 32 + lane];
                            any = 1u;
                        }
                    }
                    if (!any) break;
#pragma unroll
                    for (int j = 0; j < 4; ++j) {      // consume after all issued
                        if (act[j]) {
                            va[j].x += v[j].x; va[j].y += v[j].y;
                            va[j].z += v[j].z; va[j].w += v[j].w;
                            ++ep[j];
                        }
                    }
                }
#pragma unroll
                for (int j = 0; j < 4; ++j) {
                    int r = rb + j;
                    *reinterpret_cast<uint2*>(&As[r * APITCH + 2 * lane]) =
                        make_uint2(pack_h2(va[j].x * inv[j], va[j].y * inv[j]),
                                   pack_h2(va[j].z * inv[j], va[j].w * inv[j]));
                }
            }
        }
        CP_WAIT0();
        __syncthreads();
        // ---- MMA: 8 k16-steps, ldmatrix operands ----
#pragma unroll
        for (int ks = 0; ks < 8; ++ks) {
            uint32_t af0[4], af1[4], bf0[4], bf1[4];
            LDSM_X4(af0, aadr0 + ks * 32);
            LDSM_X4(af1, aadr1 + ks * 32);
            LDSM_X4_T(bf0, badr0 + ks * 16 * BPITCH * 4);
            LDSM_X4_T(bf1, badr1 + ks * 16 * BPITCH * 4);
            mma_f16(acc[0][0], af0, bf0[0], bf0[1]);
            mma_f16(acc[0][1], af0, bf0[2], bf0[3]);
            mma_f16(acc[0][2], af0, bf1[0], bf1[1]);
            mma_f16(acc[0][3], af0, bf1[2], bf1[3]);
            mma_f16(acc[1][0], af1, bf0[0], bf0[1]);
            mma_f16(acc[1][1], af1, bf0[2], bf0[3]);
            mma_f16(acc[1][2], af1, bf1[0], bf1[1]);
            mma_f16(acc[1][3], af1, bf1[2], bf1[3]);
        }
        __syncthreads();
    }

    // ---- epilogue: write out once + fused BN stats ----
#pragma unroll
    for (int f = 0; f < 2; ++f) {
        int r0 = m0 + wm + 16 * f + gr;
#pragma unroll
        for (int g = 0; g < 4; ++g) {
            int cn = wn + 8 * g + gc * 2;
            float s0 = 0.f, q0 = 0.f, s1 = 0.f, q1 = 0.f;
            if (r0 < nrows) {
                float v0 = acc[f][g][0], v1 = acc[f][g][1];
                *reinterpret_cast<float2*>(&out[(size_t)r0 * C + cn]) = make_float2(v0, v1);
                s0 += v0; q0 += v0 * v0; s1 += v1; q1 += v1 * v1;
            }
            if (r0 + 8 < nrows) {
                float v0 = acc[f][g][2], v1 = acc[f][g][3];
                *reinterpret_cast<float2*>(&out[(size_t)(r0 + 8) * C + cn]) = make_float2(v0, v1);
                s0 += v0; q0 += v0 * v0; s1 += v1; q1 += v1 * v1;
            }
            atomicAdd(&sstat[cn], s0);
            atomicAdd(&sstat[C + cn], q0);
            atomicAdd(&sstat[cn + 1], s1);
            atomicAdd(&sstat[C + cn + 1], q1);
        }
    }
    __syncthreads();
    if (tid < 2 * C) atomicAdd(&g_stats[tid], sstat[tid]);
}

// ===================== BN finalize + normalize ===============
__global__ void bnfin_kernel(const float* __restrict__ gamma, const float* __restrict__ beta,
                             float inv_n) {
    int c = threadIdx.x;
    float mean = g_stats[c] * inv_n;
    float var  = g_stats[C + c] * inv_n - mean * mean;
    float sc   = gamma[c] * rsqrtf(var + 1e-5f);
    g_scale[c] = sc;
    g_shift[c] = beta[c] - mean * sc;
    g_stats[c] = 0.f;
    g_stats[C + c] = 0.f;
}

__global__ void norm_kernel(float* __restrict__ out, size_t n4) {
    size_t i = (size_t)blockIdx.x * blockDim.x + threadIdx.x;
    size_t stride = (size_t)gridDim.x * blockDim.x;
    const float4* sc4 = reinterpret_cast<const float4*>(g_scale);
    const float4* sh4 = reinterpret_cast<const float4*>(g_shift);
    float4* o4 = reinterpret_cast<float4*>(out);
    for (size_t j = i; j < n4; j += stride) {
        int c4 = (int)(j & 31);
        float4 v = o4[j];
        float4 a = sc4[c4], b = sh4[c4];
        v.x = v.x * a.x + b.x;
        v.y = v.y * a.y + b.y;
        v.z = v.z * a.z + b.z;
        v.w = v.w * a.w + b.w;
        o4[j] = v;
    }
}

// ===================== launch ================================
extern "C" void kernel_launch(void* const* d_in, const int* in_sizes, int n_in,
                              void* d_out, int out_size) {
    const float* x     = (const float*)d_in[0];
    const int*   row   = (const int*)d_in[1];   // JAX x64-disabled: int32
    const int*   col   = (const int*)d_in[2];
    const int*   et    = (const int*)d_in[3];
    const float* w     = (const float*)d_in[4];
    const float* gamma = (const float*)d_in[5];
    const float* beta  = (const float*)d_in[6];
    float* out = (float*)d_out;

    int nrows = in_sizes[0] / C;          // 100000
    int E     = in_sizes[1];              // 700000
    int nseg  = nrows * NET;
    int nblk  = (nseg + SCAN_BLK - 1) / SCAN_BLK;

    cudaFuncSetAttribute(fused_kernel, cudaFuncAttributeMaxDynamicSharedMemorySize,
                         (int)FUSED_SMEM);

    count_kernel<<<(E + 255) / 256, 256>>>(row, et, w, E);                 // 0
    scan_kernel<<<nblk, SCAN_BLK>>>(nseg);                                 // 1
    fill_kernel<<<(E + 255) / 256, 256>>>(row, col, et, E);                // 2
    fused_kernel<<<(nrows + 127) / 128, 512, FUSED_SMEM>>>(x, out, nrows); // 3 <- profiled
    bnfin_kernel<<<1, 128>>>(gamma, beta, 1.0f / (float)nrows);            // 4
    norm_kernel<<<2048, 256>>>(out, (size_t)nrows * 32);                   // 5
}

// round 13
// speedup vs baseline: 1.0752x; 1.0752x over previous
#include <cuda_runtime.h>
#include <cuda_fp16.h>
#include <cstdint>
#include <cstddef>

// ===================== problem constants =====================
constexpr int C    = 128;            // channels
constexpr int NET  = 7;              // edge types
constexpr int NMAX = 100000;
constexpr int NSEGMAX = NMAX * NET;  // 700000
constexpr int EMAX = 700000;
constexpr int SCAN_BLK = 1024;

// ===================== device scratch ========================
__device__ unsigned g_cnt[NSEGMAX];             // zero-init; re-zeroed by scan
__device__ unsigned g_off[NSEGMAX + 1];         // CSR offsets
__device__ unsigned g_cur[NSEGMAX];             // fill cursors
__device__ int      g_elist[EMAX];              // col index per CSR slot
__device__ unsigned g_ticket;                   // zero-init; re-zeroed by fill
__device__ unsigned long long g_state[1024];    // zero-init; re-zeroed by fill
__device__ float    g_stats[2 * C];             // zero-init; re-zeroed by bnfin
__device__ float    g_scale[C];
__device__ float    g_shift[C];

// ===================== helpers ===============================
__device__ __forceinline__ uint32_t pack_h2(float a, float b) {
    __half2 h = __floats2half2_rn(a, b);
    return *reinterpret_cast<uint32_t*>(&h);
}
__device__ __forceinline__ uint32_t smem_u32(const void* p) {
    uint32_t a;
    asm("{ .reg .u64 t; cvta.to.shared.u64 t, %1; cvt.u32.u64 %0, t; }" : "=r"(a) : "l"(p));
    return a;
}
__device__ __forceinline__ void mma_f16(float* d, const uint32_t* a, uint32_t b0, uint32_t b1) {
    asm volatile(
        "mma.sync.aligned.m16n8k16.row.col.f32.f16.f16.f32 "
        "{%0,%1,%2,%3}, {%4,%5,%6,%7}, {%8,%9}, {%0,%1,%2,%3};"
        : "+f"(d[0]), "+f"(d[1]), "+f"(d[2]), "+f"(d[3])
        : "r"(a[0]), "r"(a[1]), "r"(a[2]), "r"(a[3]), "r"(b0), "r"(b1));
}
#define LDSM_X4(r, addr)                                                        \
    asm volatile("ldmatrix.sync.aligned.m8n8.x4.shared.b16 {%0,%1,%2,%3}, [%4];"\
        : "=r"((r)[0]), "=r"((r)[1]), "=r"((r)[2]), "=r"((r)[3]) : "r"(addr))
#define LDSM_X4_T(r, addr)                                                      \
    asm volatile("ldmatrix.sync.aligned.m8n8.x4.trans.shared.b16 {%0,%1,%2,%3}, [%4];"\
        : "=r"((r)[0]), "=r"((r)[1]), "=r"((r)[2]), "=r"((r)[3]) : "r"(addr))

__device__ unsigned block_incl_scan(unsigned v, unsigned* wsum) {
    int lane = threadIdx.x & 31, wid = threadIdx.x >> 5;
#pragma unroll
    for (int d = 1; d < 32; d <<= 1) {
        unsigned n = __shfl_up_sync(0xffffffff, v, d);
        if (lane >= d) v += n;
    }
    if (lane == 31) wsum[wid] = v;
    __syncthreads();
    if (wid == 0) {
        unsigned w = wsum[lane];
#pragma unroll
        for (int d = 1; d < 32; d <<= 1) {
            unsigned n = __shfl_up_sync(0xffffffff, w, d);
            if (lane >= d) w += n;
        }
        wsum[lane] = w;
    }
    __syncthreads();
    return v + (wid > 0 ? wsum[wid - 1] : 0u);
}

// ===================== CSR build =============================
__global__ void count_kernel(const int* __restrict__ row,
                             const int* __restrict__ et, int E) {
    int e = blockIdx.x * blockDim.x + threadIdx.x;
    if (e >= E) return;
    int t = et[e];
    if (t == NET - 1) return;
    atomicAdd(&g_cnt[row[e] * NET + t], 1u);
}

// single-pass decoupled-lookback exclusive scan; also re-zeroes g_cnt
__global__ void __launch_bounds__(SCAN_BLK) scan_kernel(int nseg) {
    __shared__ unsigned wsum[32];
    __shared__ unsigned s_bid, s_total, s_prefix;
    int tid = threadIdx.x;
    if (tid == 0) s_bid = atomicAdd(&g_ticket, 1u);
    __syncthreads();
    unsigned bid = s_bid;
    int i = bid * SCAN_BLK + tid;
    unsigned v = (i < nseg) ? g_cnt[i] : 0u;
    if (i < nseg) g_cnt[i] = 0u;                 // restore for next replay
    unsigned incl = block_incl_scan(v, wsum);
    if (tid == SCAN_BLK - 1) s_total = incl;
    __syncthreads();
    if (tid == 0) {
        unsigned total = s_total;
        if (bid == 0) {
            atomicExch(&g_state[0], (2ULL << 32) | (unsigned long long)total);
            s_prefix = 0u;
        } else {
            atomicExch(&g_state[bid], (1ULL << 32) | (unsigned long long)total);
            unsigned running = 0u;
            int idx = (int)bid - 1;
            while (true) {
                unsigned long long s;
                do { s = atomicAdd(&g_state[idx], 0ULL); } while ((unsigned)(s >> 32) == 0u);
                running += (unsigned)s;
                if ((unsigned)(s >> 32) == 2u) break;
                --idx;
            }
            s_prefix = running;
            atomicExch(&g_state[bid], (2ULL << 32) | (unsigned long long)(running + total));
        }
    }
    __syncthreads();
    unsigned off = s_prefix + incl - v;
    if (i < nseg) {
        g_off[i] = off;
        g_cur[i] = off;
        if (i == nseg - 1) g_off[nseg] = off + v;
    }
}

// fill CSR edge list; also re-zeroes scan state for next replay
__global__ void fill_kernel(const int* __restrict__ row,
                            const int* __restrict__ col,
                            const int* __restrict__ et, int E) {
    int e = blockIdx.x * blockDim.x + threadIdx.x;
    if (e < 1024) g_state[e] = 0ULL;
    if (e == 0) g_ticket = 0u;
    if (e >= E) return;
    int t = et[e];
    if (t == NET - 1) return;
    int seg = row[e] * NET + t;
    unsigned pos = atomicAdd(&g_cur[seg], 1u);
    g_elist[pos] = col[e];
}

// ===================== fused aggregate + GEMM + stats ========
constexpr int APITCH = 68;       // uints per A row (272 B: ldmatrix-aligned, bank-step 4)
constexpr int BPITCH = 68;       // uints per B k-row
constexpr int ECAP   = 4096;
constexpr int OFF_AS = 0;
constexpr int OFF_BS = OFF_AS + 128 * APITCH;      // 8704
constexpr int OFF_EL = OFF_BS + 128 * BPITCH;      // 17408
constexpr int OFF_SOFF = OFF_EL + ECAP;            // 21504
constexpr int OFF_STAT = OFF_SOFF + 128 * 8;       // 22528
constexpr int SMEM_UINTS = OFF_STAT + 2 * C;       // 22784
constexpr size_t FUSED_SMEM = (size_t)SMEM_UINTS * 4;   // 91136 B

__global__ void __launch_bounds__(512, 2)
fused_kernel(const float* __restrict__ x, const float* __restrict__ w,
             float* __restrict__ out, int nrows) {
    extern __shared__ uint32_t smu[];
    uint32_t* As = smu + OFF_AS;
    uint32_t* Bs = smu + OFF_BS;
    int*      selist = reinterpret_cast<int*>(smu + OFF_EL);
    unsigned* soff = smu + OFF_SOFF;
    float*    sstat = reinterpret_cast<float*>(smu + OFF_STAT);

    const int tid = threadIdx.x;
    const int wid = tid >> 5, lane = tid & 31;
    const int m0 = blockIdx.x * 128;
    const int rlim = min(128, nrows - m0);
    const float4* x4 = reinterpret_cast<const float4*>(x);
    const float4* w4 = reinterpret_cast<const float4*>(w);

    if (tid < 2 * C) sstat[tid] = 0.f;

    // ---- stage CTA segment offsets: soff[r][j] = g_off[(m0+r)*7 + j] ----
#pragma unroll
    for (int i = 0; i < 2; ++i) {
        int idx = tid + i * 512;
        int r = idx >> 3, j = idx & 7;
        soff[idx] = (r < rlim) ? g_off[(m0 + r) * NET + j] : 0u;
    }
    __syncthreads();
    const unsigned e0   = soff[0];
    const unsigned etot = soff[(rlim - 1) * 8 + 7] - e0;
    // ---- stage edge list (coalesced); overflow falls back to global ----
    for (unsigned i = tid; i < min(etot, (unsigned)ECAP); i += 512)
        selist[i] = g_elist[e0 + i];
    __syncthreads();

    const int wm = (wid >> 2) * 32, wn = (wid & 3) * 32;
    const int gr = lane >> 2, gc = lane & 3;
    const int grp = lane >> 3, rr = lane & 7;

    const uint32_t sbase = smem_u32(smu);
    const uint32_t abase = sbase + OFF_AS * 4;
    const uint32_t bbase = sbase + OFF_BS * 4;
    uint32_t aadr0 = abase + (wm + (grp & 1) * 8 + rr) * APITCH * 4 + (grp >> 1) * 16;
    uint32_t aadr1 = aadr0 + 16 * APITCH * 4;
    uint32_t badr0 = bbase + ((grp & 1) * 8 + rr) * BPITCH * 4 + (wn + (grp >> 1) * 8) * 2;
    uint32_t badr1 = badr0 + 16 * 2;

    float acc[2][4][4];
#pragma unroll
    for (int f = 0; f < 2; ++f)
#pragma unroll
        for (int g = 0; g < 4; ++g)
#pragma unroll
            for (int q = 0; q < 4; ++q) acc[f][g][q] = 0.f;

    for (int t = 0; t < NET; ++t) {
        // ---- B_t: W[t*128+k][n] -> Bs[k][n] fp16 (plain loads: W stays L1-hot) ----
#pragma unroll
        for (int i = 0; i < 8; ++i) {
            int e = tid + i * 512;
            int k = e >> 5, n4 = e & 31;
            float4 v = w4[(size_t)(t * C + k) * 32 + n4];
            *reinterpret_cast<uint2*>(&Bs[k * BPITCH + n4 * 2]) =
                make_uint2(pack_h2(v.x, v.y), pack_h2(v.z, v.w));
        }
        // ---- A_t gather: pairwise lockstep (2 rows in flight, low reg cost) ----
        if (t == NET - 1) {
#pragma unroll
            for (int i = 0; i < 8; ++i) {
                int r = wid * 8 + i;
                float4 val = make_float4(0.f, 0.f, 0.f, 0.f);
                if (r < rlim) val = x4[(size_t)(m0 + r) * 32 + lane];
                *reinterpret_cast<uint2*>(&As[r * APITCH + 2 * lane]) =
                    make_uint2(pack_h2(val.x, val.y), pack_h2(val.z, val.w));
            }
        } else {
#pragma unroll
            for (int h = 0; h < 4; ++h) {
                int rb = wid * 8 + h * 2;
                unsigned ep0 = 0u, ee0 = 0u, ep1 = 0u, ee1 = 0u;
                if (rb < rlim)     { ep0 = soff[rb * 8 + t] - e0;      ee0 = soff[rb * 8 + t + 1] - e0; }
                if (rb + 1 < rlim) { ep1 = soff[(rb + 1) * 8 + t] - e0; ee1 = soff[(rb + 1) * 8 + t + 1] - e0; }
                float4 a0 = make_float4(0.f, 0.f, 0.f, 0.f);
                float4 a1 = make_float4(0.f, 0.f, 0.f, 0.f);
                float inv0 = 1.0f / (float)(ee0 - ep0 > 1u ? ee0 - ep0 : 1u);
                float inv1 = 1.0f / (float)(ee1 - ep1 > 1u ? ee1 - ep1 : 1u);
                while (ep0 < ee0 || ep1 < ee1) {
                    bool p0 = ep0 < ee0, p1 = ep1 < ee1;
                    float4 v0, v1;
                    if (p0) {                          // both loads issue before
                        int c = (ep0 < (unsigned)ECAP) ? selist[ep0] : g_elist[e0 + ep0];
                        v0 = x4[(size_t)c * 32 + lane];
                    }
                    if (p1) {                          // ...either FADD consumes
                        int c = (ep1 < (unsigned)ECAP) ? selist[ep1] : g_elist[e0 + ep1];
                        v1 = x4[(size_t)c * 32 + lane];
                    }
                    if (p0) {
                        a0.x += v0.x; a0.y += v0.y; a0.z += v0.z; a0.w += v0.w; ++ep0;
                    }
                    if (p1) {
                        a1.x += v1.x; a1.y += v1.y; a1.z += v1.z; a1.w += v1.w; ++ep1;
                    }
                }
                *reinterpret_cast<uint2*>(&As[rb * APITCH + 2 * lane]) =
                    make_uint2(pack_h2(a0.x * inv0, a0.y * inv0), pack_h2(a0.z * inv0, a0.w * inv0));
                *reinterpret_cast<uint2*>(&As[(rb + 1) * APITCH + 2 * lane]) =
                    make_uint2(pack_h2(a1.x * inv1, a1.y * inv1), pack_h2(a1.z * inv1, a1.w * inv1));
            }
        }
        __syncthreads();
        // ---- MMA: 8 k16-steps, ldmatrix operands ----
#pragma unroll
        for (int ks = 0; ks < 8; ++ks) {
            uint32_t af0[4], af1[4], bf0[4], bf1[4];
            LDSM_X4(af0, aadr0 + ks * 32);
            LDSM_X4(af1, aadr1 + ks * 32);
            LDSM_X4_T(bf0, badr0 + ks * 16 * BPITCH * 4);
            LDSM_X4_T(bf1, badr1 + ks * 16 * BPITCH * 4);
            mma_f16(acc[0][0], af0, bf0[0], bf0[1]);
            mma_f16(acc[0][1], af0, bf0[2], bf0[3]);
            mma_f16(acc[0][2], af0, bf1[0], bf1[1]);
            mma_f16(acc[0][3], af0, bf1[2], bf1[3]);
            mma_f16(acc[1][0], af1, bf0[0], bf0[1]);
            mma_f16(acc[1][1], af1, bf0[2], bf0[3]);
            mma_f16(acc[1][2], af1, bf1[0], bf1[1]);
            mma_f16(acc[1][3], af1, bf1[2], bf1[3]);
        }
        __syncthreads();
    }

    // ---- epilogue: write out once + fused BN stats ----
#pragma unroll
    for (int f = 0; f < 2; ++f) {
        int r0 = m0 + wm + 16 * f + gr;
#pragma unroll
        for (int g = 0; g < 4; ++g) {
            int cn = wn + 8 * g + gc * 2;
            float s0 = 0.f, q0 = 0.f, s1 = 0.f, q1 = 0.f;
            if (r0 < nrows) {
                float v0 = acc[f][g][0], v1 = acc[f][g][1];
                *reinterpret_cast<float2*>(&out[(size_t)r0 * C + cn]) = make_float2(v0, v1);
                s0 += v0; q0 += v0 * v0; s1 += v1; q1 += v1 * v1;
            }
            if (r0 + 8 < nrows) {
                float v0 = acc[f][g][2], v1 = acc[f][g][3];
                *reinterpret_cast<float2*>(&out[(size_t)(r0 + 8) * C + cn]) = make_float2(v0, v1);
                s0 += v0; q0 += v0 * v0; s1 += v1; q1 += v1 * v1;
            }
            atomicAdd(&sstat[cn], s0);
            atomicAdd(&sstat[C + cn], q0);
            atomicAdd(&sstat[cn + 1], s1);
            atomicAdd(&sstat[C + cn + 1], q1);
        }
    }
    __syncthreads();
    if (tid < 2 * C) atomicAdd(&g_stats[tid], sstat[tid]);
}

// ===================== BN finalize + normalize ===============
__global__ void bnfin_kernel(const float* __restrict__ gamma, const float* __restrict__ beta,
                             float inv_n) {
    int c = threadIdx.x;
    float mean = g_stats[c] * inv_n;
    float var  = g_stats[C + c] * inv_n - mean * mean;
    float sc   = gamma[c] * rsqrtf(var + 1e-5f);
    g_scale[c] = sc;
    g_shift[c] = beta[c] - mean * sc;
    g_stats[c] = 0.f;
    g_stats[C + c] = 0.f;
}

__global__ void norm_kernel(float* __restrict__ out, size_t n4) {
    size_t i = (size_t)blockIdx.x * blockDim.x + threadIdx.x;
    size_t stride = (size_t)gridDim.x * blockDim.x;
    const float4* sc4 = reinterpret_cast<const float4*>(g_scale);
    const float4* sh4 = reinterpret_cast<const float4*>(g_shift);
    float4* o4 = reinterpret_cast<float4*>(out);
    for (size_t j = i; j < n4; j += stride) {
        int c4 = (int)(j & 31);
        float4 v = o4[j];
        float4 a = sc4[c4], b = sh4[c4];
        v.x = v.x * a.x + b.x;
        v.y = v.y * a.y + b.y;
        v.z = v.z * a.z + b.z;
        v.w = v.w * a.w + b.w;
        o4[j] = v;
    }
}

// ===================== launch ================================
extern "C" void kernel_launch(void* const* d_in, const int* in_sizes, int n_in,
                              void* d_out, int out_size) {
    const float* x     = (const float*)d_in[0];
    const int*   row   = (const int*)d_in[1];   // JAX x64-disabled: int32
    const int*   col   = (const int*)d_in[2];
    const int*   et    = (const int*)d_in[3];
    const float* w     = (const float*)d_in[4];
    const float* gamma = (const float*)d_in[5];
    const float* beta  = (const float*)d_in[6];
    float* out = (float*)d_out;

    int nrows = in_sizes[0] / C;          // 100000
    int E     = in_sizes[1];              // 700000
    int nseg  = nrows * NET;
    int nblk  = (nseg + SCAN_BLK - 1) / SCAN_BLK;

    cudaFuncSetAttribute(fused_kernel, cudaFuncAttributeMaxDynamicSharedMemorySize,
                         (int)FUSED_SMEM);

    count_kernel<<<(E + 255) / 256, 256>>>(row, et, E);                         // 0
    scan_kernel<<<nblk, SCAN_BLK>>>(nseg);                                      // 1
    fill_kernel<<<(E + 255) / 256, 256>>>(row, col, et, E);                     // 2
    fused_kernel<<<(nrows + 127) / 128, 512, FUSED_SMEM>>>(x, w, out, nrows);   // 3 <- profiled
    bnfin_kernel<<<1, 128>>>(gamma, beta, 1.0f / (float)nrows);                 // 4
    norm_kernel<<<2048, 256>>>(out, (size_t)nrows * 32);                        // 5
}

// round 14
// speedup vs baseline: 1.2113x; 1.1266x over previous
#include <cuda_runtime.h>
#include <cuda_fp16.h>
#include <cstdint>
#include <cstddef>

// ===================== problem constants =====================
constexpr int C    = 128;            // channels
constexpr int NET  = 7;              // edge types
constexpr int NMAX = 100000;
constexpr int NPAD = 100096;         // 782 * 128 (GEMM grid coverage)
constexpr int KTOT = NET * C;        // 896
constexpr int NSEGMAX = NMAX * NET;  // 700000
constexpr int EMAX = 700000;
constexpr int SCAN_BLK = 1024;

// ===================== device scratch ========================
__device__ unsigned g_cnt[NSEGMAX];             // zero-init; re-zeroed by scan
__device__ unsigned g_off[NSEGMAX + 1];         // CSR offsets
__device__ unsigned g_cur[NSEGMAX];             // fill cursors
__device__ int      g_elist[EMAX];              // col index per CSR slot
__device__ unsigned g_ticket;                   // zero-init; re-zeroed by fill
__device__ unsigned long long g_state[1024];    // zero-init; re-zeroed by fill
__device__ float    g_stats[2 * C];             // zero-init; re-zeroed by bnfin
__device__ float    g_scale[C];
__device__ float    g_shift[C];
__device__ uint32_t g_wh[KTOT * C / 2];         // W fp16 pairs [k][n/2]  (448 KB)
__device__ uint32_t g_ah[(size_t)NPAD * (KTOT / 2)];  // A fp16 pairs [row][448u] (179 MB)

// ===================== helpers ===============================
__device__ __forceinline__ uint32_t pack_h2(float a, float b) {
    __half2 h = __floats2half2_rn(a, b);
    return *reinterpret_cast<uint32_t*>(&h);
}
__device__ __forceinline__ uint32_t smem_u32(const void* p) {
    uint32_t a;
    asm("{ .reg .u64 t; cvta.to.shared.u64 t, %1; cvt.u32.u64 %0, t; }" : "=r"(a) : "l"(p));
    return a;
}
__device__ __forceinline__ void mma_f16(float* d, const uint32_t* a, uint32_t b0, uint32_t b1) {
    asm volatile(
        "mma.sync.aligned.m16n8k16.row.col.f32.f16.f16.f32 "
        "{%0,%1,%2,%3}, {%4,%5,%6,%7}, {%8,%9}, {%0,%1,%2,%3};"
        : "+f"(d[0]), "+f"(d[1]), "+f"(d[2]), "+f"(d[3])
        : "r"(a[0]), "r"(a[1]), "r"(a[2]), "r"(a[3]), "r"(b0), "r"(b1));
}
#define LDSM_X4(r, addr)                                                        \
    asm volatile("ldmatrix.sync.aligned.m8n8.x4.shared.b16 {%0,%1,%2,%3}, [%4];"\
        : "=r"((r)[0]), "=r"((r)[1]), "=r"((r)[2]), "=r"((r)[3]) : "r"(addr))
#define LDSM_X4_T(r, addr)                                                      \
    asm volatile("ldmatrix.sync.aligned.m8n8.x4.trans.shared.b16 {%0,%1,%2,%3}, [%4];"\
        : "=r"((r)[0]), "=r"((r)[1]), "=r"((r)[2]), "=r"((r)[3]) : "r"(addr))
__device__ __forceinline__ void cp_async16(uint32_t dst, const void* src) {
    asm volatile("cp.async.ca.shared.global [%0], [%1], 16;" :: "r"(dst), "l"(src));
}
#define CP_COMMIT() asm volatile("cp.async.commit_group;" ::: "memory")
#define CP_WAIT(n)  asm volatile("cp.async.wait_group %0;" :: "n"(n) : "memory")

__device__ unsigned block_incl_scan(unsigned v, unsigned* wsum) {
    int lane = threadIdx.x & 31, wid = threadIdx.x >> 5;
#pragma unroll
    for (int d = 1; d < 32; d <<= 1) {
        unsigned n = __shfl_up_sync(0xffffffff, v, d);
        if (lane >= d) v += n;
    }
    if (lane == 31) wsum[wid] = v;
    __syncthreads();
    if (wid == 0) {
        unsigned w = wsum[lane];
#pragma unroll
        for (int d = 1; d < 32; d <<= 1) {
            unsigned n = __shfl_up_sync(0xffffffff, w, d);
            if (lane >= d) w += n;
        }
        wsum[lane] = w;
    }
    __syncthreads();
    return v + (wid > 0 ? wsum[wid - 1] : 0u);
}

// ===================== CSR build =============================
// also packs W to fp16 [k][n] (first 57344 threads)
__global__ void count_kernel(const int* __restrict__ row,
                             const int* __restrict__ et,
                             const float* __restrict__ w, int E) {
    int e = blockIdx.x * blockDim.x + threadIdx.x;
    if (e < KTOT * C / 2) {
        float2 v = reinterpret_cast<const float2*>(w)[e];
        g_wh[e] = pack_h2(v.x, v.y);
    }
    if (e >= E) return;
    int t = et[e];
    if (t == NET - 1) return;
    atomicAdd(&g_cnt[row[e] * NET + t], 1u);
}

// single-pass decoupled-lookback exclusive scan; also re-zeroes g_cnt
__global__ void __launch_bounds__(SCAN_BLK) scan_kernel(int nseg) {
    __shared__ unsigned wsum[32];
    __shared__ unsigned s_bid, s_total, s_prefix;
    int tid = threadIdx.x;
    if (tid == 0) s_bid = atomicAdd(&g_ticket, 1u);
    __syncthreads();
    unsigned bid = s_bid;
    int i = bid * SCAN_BLK + tid;
    unsigned v = (i < nseg) ? g_cnt[i] : 0u;
    if (i < nseg) g_cnt[i] = 0u;                 // restore for next replay
    unsigned incl = block_incl_scan(v, wsum);
    if (tid == SCAN_BLK - 1) s_total = incl;
    __syncthreads();
    if (tid == 0) {
        unsigned total = s_total;
        if (bid == 0) {
            atomicExch(&g_state[0], (2ULL << 32) | (unsigned long long)total);
            s_prefix = 0u;
        } else {
            atomicExch(&g_state[bid], (1ULL << 32) | (unsigned long long)total);
            unsigned running = 0u;
            int idx = (int)bid - 1;
            while (true) {
                unsigned long long s;
                do { s = atomicAdd(&g_state[idx], 0ULL); } while ((unsigned)(s >> 32) == 0u);
                running += (unsigned)s;
                if ((unsigned)(s >> 32) == 2u) break;
                --idx;
            }
            s_prefix = running;
            atomicExch(&g_state[bid], (2ULL << 32) | (unsigned long long)(running + total));
        }
    }
    __syncthreads();
    unsigned off = s_prefix + incl - v;
    if (i < nseg) {
        g_off[i] = off;
        g_cur[i] = off;
        if (i == nseg - 1) g_off[nseg] = off + v;
    }
}

// fill CSR edge list; also re-zeroes scan state for next replay
__global__ void fill_kernel(const int* __restrict__ row,
                            const int* __restrict__ col,
                            const int* __restrict__ et, int E) {
    int e = blockIdx.x * blockDim.x + threadIdx.x;
    if (e < 1024) g_state[e] = 0ULL;
    if (e == 0) g_ticket = 0u;
    if (e >= E) return;
    int t = et[e];
    if (t == NET - 1) return;
    int seg = row[e] * NET + t;
    unsigned pos = atomicAdd(&g_cur[seg], 1u);
    g_elist[pos] = col[e];
}

// ===================== gather: warp-per-node, no barriers ====
// Writes A[row][896] fp16: slots 0..5 = mean of x[neighbors], slot 6 = x[row].
__global__ void __launch_bounds__(256) gather_kernel(const float* __restrict__ x, int nrows) {
    int wrp = (blockIdx.x * 256 + threadIdx.x) >> 5;
    int lane = threadIdx.x & 31;
    if (wrp >= nrows) return;
    const float4* x4 = reinterpret_cast<const float4*>(x);
    uint32_t* arow = g_ah + (size_t)wrp * (KTOT / 2);
    // self slot (t = 6)
    float4 v = x4[(size_t)wrp * 32 + lane];
    *reinterpret_cast<uint2*>(&arow[6 * 64 + lane * 2]) =
        make_uint2(pack_h2(v.x, v.y), pack_h2(v.z, v.w));
    int base = wrp * NET;
#pragma unroll
    for (int t = 0; t < NET - 1; ++t) {
        unsigned beg = g_off[base + t], end = g_off[base + t + 1];
        float4 a = make_float4(0.f, 0.f, 0.f, 0.f);
        for (unsigned e = beg; e < end; ++e) {
            int c = g_elist[e];
            float4 xv = x4[(size_t)c * 32 + lane];
            a.x += xv.x; a.y += xv.y; a.z += xv.z; a.w += xv.w;
        }
        if (end > beg) {
            float inv = 1.0f / (float)(end - beg);
            a.x *= inv; a.y *= inv; a.z *= inv; a.w *= inv;
        }
        *reinterpret_cast<uint2*>(&arow[t * 64 + lane * 2]) =
            make_uint2(pack_h2(a.x, a.y), pack_h2(a.z, a.w));
    }
}

// ===================== pipelined GEMM + BN stats =============
// CTA 128 rows x 128 cols, 512 threads. K = 896 in 14 chunks of 64 halfs,
// double-buffered via cp.async. Same proven ldmatrix/mma core.
constexpr int AP2 = 36;          // uints per A chunk row (144 B: aligned, bank-step 4)
constexpr int BP2 = 68;          // uints per B k-row (272 B)
constexpr int ASTAGE_B = 128 * AP2 * 4;    // 18432
constexpr int BSTAGE_B = 64 * BP2 * 4;     // 17408
constexpr int OFF_B0 = 2 * ASTAGE_B;       // 36864
constexpr int OFF_STAT_B = OFF_B0 + 2 * BSTAGE_B;  // 71680
constexpr size_t GEMM_SMEM = OFF_STAT_B + 2 * C * 4;  // 72704 B

__global__ void __launch_bounds__(512, 2)
gemm_kernel(float* __restrict__ out, int nrows) {
    extern __shared__ uint32_t smu[];
    float* sstat = reinterpret_cast<float*>(smu + OFF_STAT_B / 4);

    const int tid = threadIdx.x;
    const int wid = tid >> 5, lane = tid & 31;
    const int m0 = blockIdx.x * 128;
    if (tid < 2 * C) sstat[tid] = 0.f;

    const uint32_t sbase = smem_u32(smu);
    const int wm = (wid >> 2) * 32, wn = (wid & 3) * 32;
    const int gr = lane >> 2, gc = lane & 3;
    const int grp = lane >> 3, rr = lane & 7;

    // per-thread ldmatrix offsets (relative to stage base)
    const uint32_t aoff0 = (wm + (grp & 1) * 8 + rr) * (AP2 * 4) + (grp >> 1) * 16;
    const uint32_t aoff1 = aoff0 + 16 * (AP2 * 4);
    const uint32_t boff0 = ((grp & 1) * 8 + rr) * (BP2 * 4) + (wn + (grp >> 1) * 8) * 2;
    const uint32_t boff1 = boff0 + 32;

    // cp.async source/dest precomputed indices
    const int ar = tid >> 3, apos = tid & 7;        // A: 1024 chunks, 2 iters
    const int bk = tid >> 4, bpos = tid & 15;       // B: 1024 chunks, 2 iters

    auto load_chunk = [&](int c, int which) {
        uint32_t abuf = sbase + which * ASTAGE_B;
        uint32_t bbuf = sbase + OFF_B0 + which * BSTAGE_B;
#pragma unroll
        for (int j = 0; j < 2; ++j) {
            int r = ar + j * 64;
            cp_async16(abuf + r * (AP2 * 4) + apos * 16,
                       g_ah + (size_t)(m0 + r) * (KTOT / 2) + c * 32 + apos * 4);
        }
#pragma unroll
        for (int j = 0; j < 2; ++j) {
            int kl = bk + j * 32;
            cp_async16(bbuf + kl * (BP2 * 4) + bpos * 16,
                       g_wh + (size_t)(c * 64 + kl) * 64 + bpos * 4);
        }
    };

    float acc[2][4][4];
#pragma unroll
    for (int f = 0; f < 2; ++f)
#pragma unroll
        for (int g = 0; g < 4; ++g)
#pragma unroll
            for (int q = 0; q < 4; ++q) acc[f][g][q] = 0.f;

    load_chunk(0, 0);
    CP_COMMIT();

    for (int c = 0; c < 14; ++c) {
        if (c + 1 < 14) {
            load_chunk(c + 1, (c + 1) & 1);
            CP_COMMIT();
            CP_WAIT(1);
        } else {
            CP_WAIT(0);
        }
        __syncthreads();
        uint32_t abuf = sbase + (c & 1) * ASTAGE_B;
        uint32_t bbuf = sbase + OFF_B0 + (c & 1) * BSTAGE_B;
#pragma unroll
        for (int ks = 0; ks < 4; ++ks) {
            uint32_t af0[4], af1[4], bf0[4], bf1[4];
            LDSM_X4(af0, abuf + aoff0 + ks * 32);
            LDSM_X4(af1, abuf + aoff1 + ks * 32);
            LDSM_X4_T(bf0, bbuf + boff0 + ks * 16 * (BP2 * 4));
            LDSM_X4_T(bf1, bbuf + boff1 + ks * 16 * (BP2 * 4));
            mma_f16(acc[0][0], af0, bf0[0], bf0[1]);
            mma_f16(acc[0][1], af0, bf0[2], bf0[3]);
            mma_f16(acc[0][2], af0, bf1[0], bf1[1]);
            mma_f16(acc[0][3], af0, bf1[2], bf1[3]);
            mma_f16(acc[1][0], af1, bf0[0], bf0[1]);
            mma_f16(acc[1][1], af1, bf0[2], bf0[3]);
            mma_f16(acc[1][2], af1, bf1[0], bf1[1]);
            mma_f16(acc[1][3], af1, bf1[2], bf1[3]);
        }
        __syncthreads();
    }

    // ---- epilogue: write out once + fused BN stats ----
#pragma unroll
    for (int f = 0; f < 2; ++f) {
        int r0 = m0 + wm + 16 * f + gr;
#pragma unroll
        for (int g = 0; g < 4; ++g) {
            int cn = wn + 8 * g + gc * 2;
            float s0 = 0.f, q0 = 0.f, s1 = 0.f, q1 = 0.f;
            if (r0 < nrows) {
                float v0 = acc[f][g][0], v1 = acc[f][g][1];
                *reinterpret_cast<float2*>(&out[(size_t)r0 * C + cn]) = make_float2(v0, v1);
                s0 += v0; q0 += v0 * v0; s1 += v1; q1 += v1 * v1;
            }
            if (r0 + 8 < nrows) {
                float v0 = acc[f][g][2], v1 = acc[f][g][3];
                *reinterpret_cast<float2*>(&out[(size_t)(r0 + 8) * C + cn]) = make_float2(v0, v1);
                s0 += v0; q0 += v0 * v0; s1 += v1; q1 += v1 * v1;
            }
            atomicAdd(&sstat[cn], s0);
            atomicAdd(&sstat[C + cn], q0);
            atomicAdd(&sstat[cn + 1], s1);
            atomicAdd(&sstat[C + cn + 1], q1);
        }
    }
    __syncthreads();
    if (tid < 2 * C) atomicAdd(&g_stats[tid], sstat[tid]);
}

// ===================== BN finalize + normalize ===============
__global__ void bnfin_kernel(const float* __restrict__ gamma, const float* __restrict__ beta,
                             float inv_n) {
    int c = threadIdx.x;
    float mean = g_stats[c] * inv_n;
    float var  = g_stats[C + c] * inv_n - mean * mean;
    float sc   = gamma[c] * rsqrtf(var + 1e-5f);
    g_scale[c] = sc;
    g_shift[c] = beta[c] - mean * sc;
    g_stats[c] = 0.f;
    g_stats[C + c] = 0.f;
}

__global__ void norm_kernel(float* __restrict__ out, size_t n4) {
    size_t i = (size_t)blockIdx.x * blockDim.x + threadIdx.x;
    size_t stride = (size_t)gridDim.x * blockDim.x;
    const float4* sc4 = reinterpret_cast<const float4*>(g_scale);
    const float4* sh4 = reinterpret_cast<const float4*>(g_shift);
    float4* o4 = reinterpret_cast<float4*>(out);
    for (size_t j = i; j < n4; j += stride) {
        int c4 = (int)(j & 31);
        float4 v = o4[j];
        float4 a = sc4[c4], b = sh4[c4];
        v.x = v.x * a.x + b.x;
        v.y = v.y * a.y + b.y;
        v.z = v.z * a.z + b.z;
        v.w = v.w * a.w + b.w;
        o4[j] = v;
    }
}

// ===================== launch ================================
extern "C" void kernel_launch(void* const* d_in, const int* in_sizes, int n_in,
                              void* d_out, int out_size) {
    const float* x     = (const float*)d_in[0];
    const int*   row   = (const int*)d_in[1];   // JAX x64-disabled: int32
    const int*   col   = (const int*)d_in[2];
    const int*   et    = (const int*)d_in[3];
    const float* w     = (const float*)d_in[4];
    const float* gamma = (const float*)d_in[5];
    const float* beta  = (const float*)d_in[6];
    float* out = (float*)d_out;

    int nrows = in_sizes[0] / C;          // 100000
    int E     = in_sizes[1];              // 700000
    int nseg  = nrows * NET;
    int nblk  = (nseg + SCAN_BLK - 1) / SCAN_BLK;

    cudaFuncSetAttribute(gemm_kernel, cudaFuncAttributeMaxDynamicSharedMemorySize,
                         (int)GEMM_SMEM);

    count_kernel<<<(E + 255) / 256, 256>>>(row, et, w, E);                      // 0
    scan_kernel<<<nblk, SCAN_BLK>>>(nseg);                                      // 1
    fill_kernel<<<(E + 255) / 256, 256>>>(row, col, et, E);                     // 2
    gather_kernel<<<(nrows * 32 + 255) / 256, 256>>>(x, nrows);                 // 3 <- profiled
    gemm_kernel<<<(nrows + 127) / 128, 512, GEMM_SMEM>>>(out, nrows);           // 4
    bnfin_kernel<<<1, 128>>>(gamma, beta, 1.0f / (float)nrows);                 // 5
    norm_kernel<<<2048, 256>>>(out, (size_t)nrows * 32);                        // 6
}

// round 15
// speedup vs baseline: 1.2285x; 1.0142x over previous
#include <cuda_runtime.h>
#include <cuda_fp16.h>
#include <cstdint>
#include <cstddef>

// ===================== problem constants =====================
constexpr int C    = 128;            // channels
constexpr int NET  = 7;              // edge types
constexpr int NMAX = 100000;
constexpr int NPAD = 100096;         // 782 * 128 (GEMM grid coverage)
constexpr int KTOT = NET * C;        // 896
constexpr int NSEGMAX = NMAX * NET;  // 700000
constexpr int EMAX = 700000;
constexpr int SCAN_BLK = 1024;

// ===================== device scratch ========================
__device__ unsigned g_cnt[NSEGMAX];             // zero-init; re-zeroed by scan
__device__ unsigned g_off[NSEGMAX + 1];         // CSR offsets
__device__ unsigned g_cur[NSEGMAX];             // fill cursors
__device__ int      g_elist[EMAX];              // col index per CSR slot
__device__ unsigned g_ticket;                   // zero-init; re-zeroed by fill
__device__ unsigned long long g_state[1024];    // zero-init; re-zeroed by fill
__device__ float    g_stats[2 * C];             // zeroed by count each replay
__device__ uint32_t g_wh[KTOT * C / 2];         // W fp16 pairs [k][n/2]  (448 KB)
__device__ uint32_t g_ah[(size_t)NPAD * (KTOT / 2)];  // A fp16 pairs [row][448u] (179 MB)

// ===================== helpers ===============================
__device__ __forceinline__ uint32_t pack_h2(float a, float b) {
    __half2 h = __floats2half2_rn(a, b);
    return *reinterpret_cast<uint32_t*>(&h);
}
__device__ __forceinline__ uint32_t smem_u32(const void* p) {
    uint32_t a;
    asm("{ .reg .u64 t; cvta.to.shared.u64 t, %1; cvt.u32.u64 %0, t; }" : "=r"(a) : "l"(p));
    return a;
}
__device__ __forceinline__ void mma_f16(float* d, const uint32_t* a, uint32_t b0, uint32_t b1) {
    asm volatile(
        "mma.sync.aligned.m16n8k16.row.col.f32.f16.f16.f32 "
        "{%0,%1,%2,%3}, {%4,%5,%6,%7}, {%8,%9}, {%0,%1,%2,%3};"
        : "+f"(d[0]), "+f"(d[1]), "+f"(d[2]), "+f"(d[3])
        : "r"(a[0]), "r"(a[1]), "r"(a[2]), "r"(a[3]), "r"(b0), "r"(b1));
}
#define LDSM_X4(r, addr)                                                        \
    asm volatile("ldmatrix.sync.aligned.m8n8.x4.shared.b16 {%0,%1,%2,%3}, [%4];"\
        : "=r"((r)[0]), "=r"((r)[1]), "=r"((r)[2]), "=r"((r)[3]) : "r"(addr))
#define LDSM_X4_T(r, addr)                                                      \
    asm volatile("ldmatrix.sync.aligned.m8n8.x4.trans.shared.b16 {%0,%1,%2,%3}, [%4];"\
        : "=r"((r)[0]), "=r"((r)[1]), "=r"((r)[2]), "=r"((r)[3]) : "r"(addr))
__device__ __forceinline__ void cp_async16(uint32_t dst, const void* src) {
    asm volatile("cp.async.cg.shared.global [%0], [%1], 16;" :: "r"(dst), "l"(src));
}
#define CP_COMMIT() asm volatile("cp.async.commit_group;" ::: "memory")
#define CP_WAIT(n)  asm volatile("cp.async.wait_group %0;" :: "n"(n) : "memory")

__device__ unsigned block_incl_scan(unsigned v, unsigned* wsum) {
    int lane = threadIdx.x & 31, wid = threadIdx.x >> 5;
#pragma unroll
    for (int d = 1; d < 32; d <<= 1) {
        unsigned n = __shfl_up_sync(0xffffffff, v, d);
        if (lane >= d) v += n;
    }
    if (lane == 31) wsum[wid] = v;
    __syncthreads();
    if (wid == 0) {
        unsigned w = wsum[lane];
#pragma unroll
        for (int d = 1; d < 32; d <<= 1) {
            unsigned n = __shfl_up_sync(0xffffffff, w, d);
            if (lane >= d) w += n;
        }
        wsum[lane] = w;
    }
    __syncthreads();
    return v + (wid > 0 ? wsum[wid - 1] : 0u);
}

// ===================== CSR build =============================
// packs W to fp16, zeroes BN stats, counts segments
__global__ void count_kernel(const int* __restrict__ row,
                             const int* __restrict__ et,
                             const float* __restrict__ w, int E) {
    int e = blockIdx.x * blockDim.x + threadIdx.x;
    if (e < KTOT * C / 2) {
        float2 v = reinterpret_cast<const float2*>(w)[e];
        g_wh[e] = pack_h2(v.x, v.y);
    }
    if (e < 2 * C) g_stats[e] = 0.f;
    if (e >= E) return;
    int t = et[e];
    if (t == NET - 1) return;
    atomicAdd(&g_cnt[row[e] * NET + t], 1u);
}

// single-pass decoupled-lookback exclusive scan; also re-zeroes g_cnt
__global__ void __launch_bounds__(SCAN_BLK) scan_kernel(int nseg) {
    __shared__ unsigned wsum[32];
    __shared__ unsigned s_bid, s_total, s_prefix;
    int tid = threadIdx.x;
    if (tid == 0) s_bid = atomicAdd(&g_ticket, 1u);
    __syncthreads();
    unsigned bid = s_bid;
    int i = bid * SCAN_BLK + tid;
    unsigned v = (i < nseg) ? g_cnt[i] : 0u;
    if (i < nseg) g_cnt[i] = 0u;                 // restore for next replay
    unsigned incl = block_incl_scan(v, wsum);
    if (tid == SCAN_BLK - 1) s_total = incl;
    __syncthreads();
    if (tid == 0) {
        unsigned total = s_total;
        if (bid == 0) {
            atomicExch(&g_state[0], (2ULL << 32) | (unsigned long long)total);
            s_prefix = 0u;
        } else {
            atomicExch(&g_state[bid], (1ULL << 32) | (unsigned long long)total);
            unsigned running = 0u;
            int idx = (int)bid - 1;
            while (true) {
                unsigned long long s;
                do { s = atomicAdd(&g_state[idx], 0ULL); } while ((unsigned)(s >> 32) == 0u);
                running += (unsigned)s;
                if ((unsigned)(s >> 32) == 2u) break;
                --idx;
            }
            s_prefix = running;
            atomicExch(&g_state[bid], (2ULL << 32) | (unsigned long long)(running + total));
        }
    }
    __syncthreads();
    unsigned off = s_prefix + incl - v;
    if (i < nseg) {
        g_off[i] = off;
        g_cur[i] = off;
        if (i == nseg - 1) g_off[nseg] = off + v;
    }
}

// fill CSR edge list; also re-zeroes scan state for next replay
__global__ void fill_kernel(const int* __restrict__ row,
                            const int* __restrict__ col,
                            const int* __restrict__ et, int E) {
    int e = blockIdx.x * blockDim.x + threadIdx.x;
    if (e < 1024) g_state[e] = 0ULL;
    if (e == 0) g_ticket = 0u;
    if (e >= E) return;
    int t = et[e];
    if (t == NET - 1) return;
    int seg = row[e] * NET + t;
    unsigned pos = atomicAdd(&g_cur[seg], 1u);
    g_elist[pos] = col[e];
}

// ===================== gather: warp-per-node, no barriers ====
__global__ void __launch_bounds__(256) gather_kernel(const float* __restrict__ x, int nrows) {
    int wrp = (blockIdx.x * 256 + threadIdx.x) >> 5;
    int lane = threadIdx.x & 31;
    if (wrp >= nrows) return;
    const float4* x4 = reinterpret_cast<const float4*>(x);
    uint32_t* arow = g_ah + (size_t)wrp * (KTOT / 2);
    // self slot (t = 6)
    float4 v = x4[(size_t)wrp * 32 + lane];
    *reinterpret_cast<uint2*>(&arow[6 * 64 + lane * 2]) =
        make_uint2(pack_h2(v.x, v.y), pack_h2(v.z, v.w));
    int base = wrp * NET;
#pragma unroll
    for (int t = 0; t < NET - 1; ++t) {
        unsigned beg = g_off[base + t], end = g_off[base + t + 1];
        float4 a = make_float4(0.f, 0.f, 0.f, 0.f);
        for (unsigned e = beg; e < end; ++e) {
            int c = g_elist[e];
            float4 xv = x4[(size_t)c * 32 + lane];
            a.x += xv.x; a.y += xv.y; a.z += xv.z; a.w += xv.w;
        }
        if (end > beg) {
            float inv = 1.0f / (float)(end - beg);
            a.x *= inv; a.y *= inv; a.z *= inv; a.w *= inv;
        }
        *reinterpret_cast<uint2*>(&arow[t * 64 + lane * 2]) =
            make_uint2(pack_h2(a.x, a.y), pack_h2(a.z, a.w));
    }
}

// ===================== pipelined GEMM + BN stats =============
// CTA 128x128, 512 threads, K = 14 chunks of 64 halfs, 3-stage cp.async.cg.
constexpr int AP2 = 36;          // uints per A chunk row (144 B)
constexpr int BP2 = 68;          // uints per B k-row (272 B)
constexpr int ASTAGE = 128 * AP2 * 4;      // 18432 B
constexpr int BSTAGE = 64 * BP2 * 4;       // 17408 B
constexpr int STAGE  = ASTAGE + BSTAGE;    // 35840 B
constexpr int OFF_STAT_B = 3 * STAGE;      // 107520
constexpr size_t GEMM_SMEM = OFF_STAT_B + 2 * C * 4;  // 108544 B (2 CTAs/SM)

// issue one chunk's loads into stage ss (dst offsets + src ptrs loop-invariant)
#define GEMM_LOAD(aSrc, bSrc, ss) do {                                          \
    uint32_t _ab = sbase + (ss) * STAGE;                                        \
    cp_async16(_ab + adst, (aSrc));                                             \
    cp_async16(_ab + adst + 64 * (AP2 * 4), (aSrc) + 64 * 448);                 \
    cp_async16(_ab + bdst, (bSrc));                                             \
    cp_async16(_ab + bdst + 32 * (BP2 * 4), (bSrc) + 32 * 64);                  \
    CP_COMMIT();                                                                \
} while (0)

__global__ void __launch_bounds__(512, 2)
gemm_kernel(float* __restrict__ out, int nrows) {
    extern __shared__ uint32_t smu[];
    float* sstat = reinterpret_cast<float*>(smu + OFF_STAT_B / 4);

    const int tid = threadIdx.x;
    const int wid = tid >> 5, lane = tid & 31;
    const int m0 = blockIdx.x * 128;
    if (tid < 2 * C) sstat[tid] = 0.f;

    const uint32_t sbase = smem_u32(smu);
    const int wm = (wid >> 2) * 32, wn = (wid & 3) * 32;
    const int gr = lane >> 2, gc = lane & 3;
    const int grp = lane >> 3, rr = lane & 7;

    const uint32_t aoff0 = (wm + (grp & 1) * 8 + rr) * (AP2 * 4) + (grp >> 1) * 16;
    const uint32_t aoff1 = aoff0 + 16 * (AP2 * 4);
    const uint32_t boff0 = ASTAGE + ((grp & 1) * 8 + rr) * (BP2 * 4) + (wn + (grp >> 1) * 8) * 2;
    const uint32_t boff1 = boff0 + 32;

    const int ar = tid >> 3, apos = tid & 7;     // A: 8 thr/row, rows ar, ar+64
    const int bk = tid >> 4, bpos = tid & 15;    // B: 16 thr/row, rows bk, bk+32
    const uint32_t adst = ar * (AP2 * 4) + apos * 16;
    const uint32_t bdst = ASTAGE + bk * (BP2 * 4) + bpos * 16;
    const uint32_t* aS = g_ah + (size_t)(m0 + ar) * 448 + apos * 4;
    const uint32_t* bS = g_wh + (size_t)bk * 64 + bpos * 4;

    float acc[2][4][4];
#pragma unroll
    for (int f = 0; f < 2; ++f)
#pragma unroll
        for (int g = 0; g < 4; ++g)
#pragma unroll
            for (int q = 0; q < 4; ++q) acc[f][g][q] = 0.f;

    GEMM_LOAD(aS, bS, 0);
    GEMM_LOAD(aS + 32, bS + 4096, 1);
    const uint32_t* aL = aS + 64;                // load head at chunk 2
    const uint32_t* bL = bS + 8192;
    int cur = 0;

    for (int c = 0; c < 14; ++c) {
        if (c < 12) {
            int nxt = (cur == 0) ? 2 : cur - 1;  // (cur+2)%3
            GEMM_LOAD(aL, bL, nxt);
            aL += 32; bL += 4096;
            CP_WAIT(2);
        } else {
            CP_WAIT(0);
        }
        __syncthreads();
        uint32_t abuf = sbase + cur * STAGE;
#pragma unroll
        for (int ks = 0; ks < 4; ++ks) {
            uint32_t af0[4], af1[4], bf0[4], bf1[4];
            LDSM_X4(af0, abuf + aoff0 + ks * 32);
            LDSM_X4(af1, abuf + aoff1 + ks * 32);
            LDSM_X4_T(bf0, abuf + boff0 + ks * 16 * (BP2 * 4));
            LDSM_X4_T(bf1, abuf + boff1 + ks * 16 * (BP2 * 4));
            mma_f16(acc[0][0], af0, bf0[0], bf0[1]);
            mma_f16(acc[0][1], af0, bf0[2], bf0[3]);
            mma_f16(acc[0][2], af0, bf1[0], bf1[1]);
            mma_f16(acc[0][3], af0, bf1[2], bf1[3]);
            mma_f16(acc[1][0], af1, bf0[0], bf0[1]);
            mma_f16(acc[1][1], af1, bf0[2], bf0[3]);
            mma_f16(acc[1][2], af1, bf1[0], bf1[1]);
            mma_f16(acc[1][3], af1, bf1[2], bf1[3]);
        }
        __syncthreads();
        cur = (cur == 2) ? 0 : cur + 1;
    }

    // ---- epilogue: write out once + fused BN stats ----
#pragma unroll
    for (int f = 0; f < 2; ++f) {
        int r0 = m0 + wm + 16 * f + gr;
#pragma unroll
        for (int g = 0; g < 4; ++g) {
            int cn = wn + 8 * g + gc * 2;
            float s0 = 0.f, q0 = 0.f, s1 = 0.f, q1 = 0.f;
            if (r0 < nrows) {
                float v0 = acc[f][g][0], v1 = acc[f][g][1];
                *reinterpret_cast<float2*>(&out[(size_t)r0 * C + cn]) = make_float2(v0, v1);
                s0 += v0; q0 += v0 * v0; s1 += v1; q1 += v1 * v1;
            }
            if (r0 + 8 < nrows) {
                float v0 = acc[f][g][2], v1 = acc[f][g][3];
                *reinterpret_cast<float2*>(&out[(size_t)(r0 + 8) * C + cn]) = make_float2(v0, v1);
                s0 += v0; q0 += v0 * v0; s1 += v1; q1 += v1 * v1;
            }
            atomicAdd(&sstat[cn], s0);
            atomicAdd(&sstat[C + cn], q0);
            atomicAdd(&sstat[cn + 1], s1);
            atomicAdd(&sstat[C + cn + 1], q1);
        }
    }
    __syncthreads();
    if (tid < 2 * C) atomicAdd(&g_stats[tid], sstat[tid]);
}

// ===================== normalize (scale/shift per block) =====
__global__ void norm_kernel(float* __restrict__ out,
                            const float* __restrict__ gamma,
                            const float* __restrict__ beta,
                            float inv_n, size_t n4) {
    __shared__ float ssc[C], ssh[C];
    int tid = threadIdx.x;
    if (tid < C) {
        float mean = g_stats[tid] * inv_n;
        float var  = g_stats[C + tid] * inv_n - mean * mean;
        float sc   = gamma[tid] * rsqrtf(var + 1e-5f);
        ssc[tid] = sc;
        ssh[tid] = beta[tid] - mean * sc;
    }
    __syncthreads();
    size_t i = (size_t)blockIdx.x * blockDim.x + tid;
    size_t stride = (size_t)gridDim.x * blockDim.x;
    const float4* sc4 = reinterpret_cast<const float4*>(ssc);
    const float4* sh4 = reinterpret_cast<const float4*>(ssh);
    float4* o4 = reinterpret_cast<float4*>(out);
    for (size_t j = i; j < n4; j += stride) {
        int c4 = (int)(j & 31);
        float4 v = o4[j];
        float4 a = sc4[c4], b = sh4[c4];
        v.x = v.x * a.x + b.x;
        v.y = v.y * a.y + b.y;
        v.z = v.z * a.z + b.z;
        v.w = v.w * a.w + b.w;
        o4[j] = v;
    }
}

// ===================== launch ================================
extern "C" void kernel_launch(void* const* d_in, const int* in_sizes, int n_in,
                              void* d_out, int out_size) {
    const float* x     = (const float*)d_in[0];
    const int*   row   = (const int*)d_in[1];   // JAX x64-disabled: int32
    const int*   col   = (const int*)d_in[2];
    const int*   et    = (const int*)d_in[3];
    const float* w     = (const float*)d_in[4];
    const float* gamma = (const float*)d_in[5];
    const float* beta  = (const float*)d_in[6];
    float* out = (float*)d_out;

    int nrows = in_sizes[0] / C;          // 100000
    int E     = in_sizes[1];              // 700000
    int nseg  = nrows * NET;
    int nblk  = (nseg + SCAN_BLK - 1) / SCAN_BLK;

    cudaFuncSetAttribute(gemm_kernel, cudaFuncAttributeMaxDynamicSharedMemorySize,
                         (int)GEMM_SMEM);

    count_kernel<<<(E + 255) / 256, 256>>>(row, et, w, E);                      // 0
    scan_kernel<<<nblk, SCAN_BLK>>>(nseg);                                      // 1
    fill_kernel<<<(E + 255) / 256, 256>>>(row, col, et, E);                     // 2
    gather_kernel<<<(nrows * 32 + 255) / 256, 256>>>(x, nrows);                 // 3 <- profiled
    gemm_kernel<<<(nrows + 127) / 128, 512, GEMM_SMEM>>>(out, nrows);           // 4
    norm_kernel<<<2048, 256>>>(out, gamma, beta, 1.0f / (float)nrows,
                               (size_t)nrows * 32);                             // 5
}